// round 1
// baseline (speedup 1.0000x reference)
#include <cuda_runtime.h>

// ---------------- scratch (device globals; no allocation allowed) ----------------
#define NB 64
__device__ float g_buf1[NB*16*128*128]; // enc conv1 out (pre-BN)
__device__ float g_buf2[NB*16*64*64];   // enc conv2 out
__device__ float g_buf3[NB*32*32*32];   // enc conv3 out (q_in pre-BN)
__device__ float g_buf4[NB*32*32*32];   // q_out
__device__ float g_buf5[NB*16*64*64];   // dec convT1 out
__device__ float g_buf6[NB*16*128*128]; // dec convT2 out
__device__ float g_buf7[NB*256*256];    // dec convT3 out (pre-BN)
__device__ float g_sum[6*32];
__device__ float g_sq[6*32];
__device__ float g_scale[6*32];
__device__ float g_shift[6*32];
__device__ float g_cnorm[512];
__device__ float g_loss[2];   // [0]=quant SSE, [1]=recon SSE

__device__ __forceinline__ float warp_red(float v) {
    #pragma unroll
    for (int o = 16; o; o >>= 1) v += __shfl_down_sync(0xffffffffu, v, o);
    return v;
}

// ---------------- tiny helpers ----------------
__global__ void zero_k() {
    int i = threadIdx.x;
    if (i < 192) { g_sum[i] = 0.f; g_sq[i] = 0.f; }
    if (i < 2) g_loss[i] = 0.f;
}

__global__ void cnorm_k(const float* __restrict__ cb) {
    int k = blockIdx.x * blockDim.x + threadIdx.x;
    if (k < 512) {
        float s = 0.f;
        #pragma unroll
        for (int c = 0; c < 32; c++) { float v = cb[k*32 + c]; s = fmaf(v, v, s); }
        g_cnorm[k] = s;
    }
}

__global__ void bnfin_k(const float* __restrict__ sum_, const float* __restrict__ sq_,
                        const float* __restrict__ g, const float* __restrict__ be,
                        float* __restrict__ sc, float* __restrict__ sh, float cnt) {
    int c = threadIdx.x;
    float m = sum_[c] / cnt;
    float var = sq_[c] / cnt - m * m;
    float s = g[c] * rsqrtf(var + 1e-5f);
    sc[c] = s;
    sh[c] = be[c] - m * s;
}

// ---------------- strided conv (k=4,s=2,p=1), BN-apply fused on input, BN-stats on output ----------------
template<int CIN, int COUT, int HO, int WO, bool PRE>
__global__ void conv_s2_k(const float* __restrict__ in, const float* __restrict__ w,
                          const float* __restrict__ bias,
                          const float* __restrict__ psc, const float* __restrict__ psh,
                          float* __restrict__ out,
                          float* __restrict__ gsum, float* __restrict__ gsq) {
    constexpr int HI = HO * 2, WI = WO * 2;
    __shared__ float ws[CIN * 16 * COUT];   // [ic][ky*4+kx][oc]
    __shared__ float ssum[COUT], ssq[COUT];
    int tid = threadIdx.x;
    for (int i = tid; i < CIN * 16 * COUT; i += blockDim.x) {
        int oc = i % COUT; int r = i / COUT; int k = r & 15; int ic = r >> 4;
        ws[i] = w[(oc * CIN + ic) * 16 + k];
    }
    if (tid < COUT) { ssum[tid] = 0.f; ssq[tid] = 0.f; }
    __syncthreads();

    int b = blockIdx.y;
    int pix = blockIdx.x * blockDim.x + tid;
    if (pix >= HO * WO) return;
    int oy = pix / WO, ox = pix % WO;

    float acc[COUT];
    #pragma unroll
    for (int oc = 0; oc < COUT; oc++) acc[oc] = bias[oc];

    const float* inb = in + (size_t)b * CIN * HI * WI;
    #pragma unroll
    for (int ic = 0; ic < CIN; ic++) {
        const float* ip = inb + (size_t)ic * HI * WI;
        float sc = 1.f, sh = 0.f;
        if constexpr (PRE) { sc = psc[ic]; sh = psh[ic]; }
        #pragma unroll
        for (int ky = 0; ky < 4; ky++) {
            int iy = 2 * oy - 1 + ky;
            if ((unsigned)iy >= (unsigned)HI) continue;
            const float* rp = ip + (size_t)iy * WI;
            #pragma unroll
            for (int kx = 0; kx < 4; kx++) {
                int ix = 2 * ox - 1 + kx;
                if ((unsigned)ix >= (unsigned)WI) continue;
                float v = rp[ix];
                if constexpr (PRE) v = fmaxf(fmaf(v, sc, sh), 0.f);
                const float* wr = &ws[(ic * 16 + ky * 4 + kx) * COUT];
                if constexpr (COUT % 4 == 0) {
                    const float4* w4 = (const float4*)wr;
                    #pragma unroll
                    for (int j = 0; j < COUT / 4; j++) {
                        float4 ww = w4[j];
                        acc[4*j+0] = fmaf(v, ww.x, acc[4*j+0]);
                        acc[4*j+1] = fmaf(v, ww.y, acc[4*j+1]);
                        acc[4*j+2] = fmaf(v, ww.z, acc[4*j+2]);
                        acc[4*j+3] = fmaf(v, ww.w, acc[4*j+3]);
                    }
                } else {
                    #pragma unroll
                    for (int oc = 0; oc < COUT; oc++) acc[oc] = fmaf(v, wr[oc], acc[oc]);
                }
            }
        }
    }

    float* ob = out + ((size_t)b * COUT) * HO * WO + pix;
    #pragma unroll
    for (int oc = 0; oc < COUT; oc++) ob[(size_t)oc * HO * WO] = acc[oc];

    int lane = tid & 31;
    #pragma unroll
    for (int oc = 0; oc < COUT; oc++) {
        float s = warp_red(acc[oc]);
        float q = warp_red(acc[oc] * acc[oc]);
        if (lane == 0) { atomicAdd(&ssum[oc], s); atomicAdd(&ssq[oc], q); }
    }
    __syncthreads();
    if (tid < COUT) { atomicAdd(&gsum[tid], ssum[tid]); atomicAdd(&gsq[tid], ssq[tid]); }
}

// ---------------- transposed conv (k=4,s=2,p=1) ----------------
template<int CIN, int COUT, int HO, int WO, bool PRE>
__global__ void convT_k(const float* __restrict__ in, const float* __restrict__ w,
                        const float* __restrict__ bias,
                        const float* __restrict__ psc, const float* __restrict__ psh,
                        float* __restrict__ out,
                        float* __restrict__ gsum, float* __restrict__ gsq) {
    constexpr int HI = HO / 2, WI = WO / 2;
    __shared__ float ws[CIN * 16 * COUT];   // [ic][ky*4+kx][oc]
    __shared__ float ssum[COUT], ssq[COUT];
    int tid = threadIdx.x;
    for (int i = tid; i < CIN * 16 * COUT; i += blockDim.x) {
        int oc = i % COUT; int r = i / COUT; int k = r & 15; int ic = r >> 4;
        ws[i] = w[(ic * COUT + oc) * 16 + k];   // torch layout [in][out][kh][kw]
    }
    if (tid < COUT) { ssum[tid] = 0.f; ssq[tid] = 0.f; }
    __syncthreads();

    int b = blockIdx.y;
    int pix = blockIdx.x * blockDim.x + tid;
    if (pix >= HO * WO) return;
    int oy = pix / WO, ox = pix % WO;
    int py = (oy + 1) & 1, px = (ox + 1) & 1;

    float acc[COUT];
    #pragma unroll
    for (int oc = 0; oc < COUT; oc++) acc[oc] = bias[oc];

    const float* inb = in + (size_t)b * CIN * HI * WI;
    #pragma unroll
    for (int ic = 0; ic < CIN; ic++) {
        const float* ip = inb + (size_t)ic * HI * WI;
        float sc = 1.f, sh = 0.f;
        if constexpr (PRE) { sc = psc[ic]; sh = psh[ic]; }
        #pragma unroll
        for (int ty = 0; ty < 2; ty++) {
            int ky = py + 2 * ty;
            int iy = (oy + 1 - ky) >> 1;
            if ((unsigned)iy >= (unsigned)HI) continue;
            const float* rp = ip + (size_t)iy * WI;
            #pragma unroll
            for (int tx = 0; tx < 2; tx++) {
                int kx = px + 2 * tx;
                int ix = (ox + 1 - kx) >> 1;
                if ((unsigned)ix >= (unsigned)WI) continue;
                float v = rp[ix];
                if constexpr (PRE) v = fmaxf(fmaf(v, sc, sh), 0.f);
                const float* wr = &ws[(ic * 16 + ky * 4 + kx) * COUT];
                if constexpr (COUT % 4 == 0) {
                    const float4* w4 = (const float4*)wr;
                    #pragma unroll
                    for (int j = 0; j < COUT / 4; j++) {
                        float4 ww = w4[j];
                        acc[4*j+0] = fmaf(v, ww.x, acc[4*j+0]);
                        acc[4*j+1] = fmaf(v, ww.y, acc[4*j+1]);
                        acc[4*j+2] = fmaf(v, ww.z, acc[4*j+2]);
                        acc[4*j+3] = fmaf(v, ww.w, acc[4*j+3]);
                    }
                } else {
                    #pragma unroll
                    for (int oc = 0; oc < COUT; oc++) acc[oc] = fmaf(v, wr[oc], acc[oc]);
                }
            }
        }
    }

    float* ob = out + ((size_t)b * COUT) * HO * WO + pix;
    #pragma unroll
    for (int oc = 0; oc < COUT; oc++) ob[(size_t)oc * HO * WO] = acc[oc];

    int lane = tid & 31;
    #pragma unroll
    for (int oc = 0; oc < COUT; oc++) {
        float s = warp_red(acc[oc]);
        float q = warp_red(acc[oc] * acc[oc]);
        if (lane == 0) { atomicAdd(&ssum[oc], s); atomicAdd(&ssq[oc], q); }
    }
    __syncthreads();
    if (tid < COUT) { atomicAdd(&gsum[tid], ssum[tid]); atomicAdd(&gsq[tid], ssq[tid]); }
}

// ---------------- quantizer: 4 threads per vector, 128 codes each ----------------
__global__ void quant_k(const float* __restrict__ q_raw, const float* __restrict__ cb,
                        float* __restrict__ qout, float* __restrict__ idx_out,
                        const float* __restrict__ sc_, const float* __restrict__ sh_) {
    int t = blockIdx.x * blockDim.x + threadIdx.x;
    int vec = t >> 2, sub = t & 3;
    if (vec >= NB * 1024) return;
    int b = vec >> 10, hw = vec & 1023;

    const float* base = q_raw + ((size_t)b * 32) * 1024 + hw;
    float z[32];
    #pragma unroll
    for (int c = 0; c < 32; c++) {
        float v = base[(size_t)c * 1024];
        z[c] = fmaxf(fmaf(v, sc_[c], sh_[c]), 0.f);   // BN+ReLU -> q_in
    }

    float best = 3.4e38f; int bi = 0x7fffffff;
    int k0 = sub * 128;
    for (int k = k0; k < k0 + 128; k++) {
        const float4* cp = (const float4*)(cb + (size_t)k * 32);
        float d0 = 0.f, d1 = 0.f, d2 = 0.f, d3 = 0.f;
        #pragma unroll
        for (int j = 0; j < 8; j++) {
            float4 c4 = __ldg(&cp[j]);
            d0 = fmaf(z[4*j+0], c4.x, d0);
            d1 = fmaf(z[4*j+1], c4.y, d1);
            d2 = fmaf(z[4*j+2], c4.z, d2);
            d3 = fmaf(z[4*j+3], c4.w, d3);
        }
        float dot = (d0 + d1) + (d2 + d3);
        float s = g_cnorm[k] - 2.f * dot;
        if (s < best) { best = s; bi = k; }
    }
    // combine across the 4 sub-lanes (lanes 4v..4v+3 in warp); tie -> lower index
    #pragma unroll
    for (int m = 1; m <= 2; m <<= 1) {
        float ob = __shfl_xor_sync(0xffffffffu, best, m);
        int obi   = __shfl_xor_sync(0xffffffffu, bi,   m);
        if (ob < best || (ob == best && obi < bi)) { best = ob; bi = obi; }
    }

    float sse = 0.f;
    if (sub == 0) {
        idx_out[vec] = (float)bi;
        float* qb = qout + ((size_t)b * 32) * 1024 + hw;
        const float* cbest = cb + (size_t)bi * 32;
        #pragma unroll
        for (int c = 0; c < 32; c++) {
            float qc = cbest[c];
            qb[(size_t)c * 1024] = qc;
            float d = qc - z[c];
            sse = fmaf(d, d, sse);
        }
    }
    sse = warp_red(sse);
    if ((threadIdx.x & 31) == 0) atomicAdd(&g_loss[0], sse);
}

// ---------------- final: BN6-apply, write output, recon SSE ----------------
__global__ void final_k(const float* __restrict__ x, float* __restrict__ dout,
                        const float* __restrict__ sc_, const float* __restrict__ sh_) {
    __shared__ float wsum[8];
    int i = blockIdx.x * blockDim.x + threadIdx.x;
    float sc = sc_[0], sh = sh_[0];
    float y = fmaf(g_buf7[i], sc, sh);
    dout[i] = y;
    float d = x[i] - y;
    float s = d * d;
    s = warp_red(s);
    if ((threadIdx.x & 31) == 0) wsum[threadIdx.x >> 5] = s;
    __syncthreads();
    if (threadIdx.x == 0) {
        float t = 0.f;
        #pragma unroll
        for (int j = 0; j < 8; j++) t += wsum[j];
        atomicAdd(&g_loss[1], t);
    }
}

__global__ void loss_k(float* __restrict__ dloss) {
    dloss[0] = 1.2f * g_loss[0] * (1.f / 2097152.f) + g_loss[1] * (1.f / 4194304.f);
}

// ---------------- launcher ----------------
extern "C" void kernel_launch(void* const* d_in, const int* in_sizes, int n_in,
                              void* d_out, int out_size) {
    const float* x      = (const float*)d_in[0];
    const float* enc_w1 = (const float*)d_in[1];
    const float* enc_b1 = (const float*)d_in[2];
    const float* enc_w2 = (const float*)d_in[3];
    const float* enc_b2 = (const float*)d_in[4];
    const float* enc_w3 = (const float*)d_in[5];
    const float* enc_b3 = (const float*)d_in[6];
    const float* enc_g1 = (const float*)d_in[7];
    const float* enc_be1= (const float*)d_in[8];
    const float* enc_g2 = (const float*)d_in[9];
    const float* enc_be2= (const float*)d_in[10];
    const float* enc_g3 = (const float*)d_in[11];
    const float* enc_be3= (const float*)d_in[12];
    const float* cb     = (const float*)d_in[13];
    const float* dec_w1 = (const float*)d_in[14];
    const float* dec_b1 = (const float*)d_in[15];
    const float* dec_w2 = (const float*)d_in[16];
    const float* dec_b2 = (const float*)d_in[17];
    const float* dec_w3 = (const float*)d_in[18];
    const float* dec_b3 = (const float*)d_in[19];
    const float* dec_g1 = (const float*)d_in[20];
    const float* dec_be1= (const float*)d_in[21];
    const float* dec_g2 = (const float*)d_in[22];
    const float* dec_be2= (const float*)d_in[23];
    const float* dec_g3 = (const float*)d_in[24];
    const float* dec_be3= (const float*)d_in[25];

    float* o = (float*)d_out;
    float* o_loss = o + 4194304;
    float* o_idx  = o + 4194305;

    static float *buf1,*buf2,*buf3,*buf4,*buf5,*buf6,*buf7,*sum,*sq,*sc,*sh;
    static bool init = false;
    if (!init) {
        cudaGetSymbolAddress((void**)&buf1, g_buf1);
        cudaGetSymbolAddress((void**)&buf2, g_buf2);
        cudaGetSymbolAddress((void**)&buf3, g_buf3);
        cudaGetSymbolAddress((void**)&buf4, g_buf4);
        cudaGetSymbolAddress((void**)&buf5, g_buf5);
        cudaGetSymbolAddress((void**)&buf6, g_buf6);
        cudaGetSymbolAddress((void**)&buf7, g_buf7);
        cudaGetSymbolAddress((void**)&sum,  g_sum);
        cudaGetSymbolAddress((void**)&sq,   g_sq);
        cudaGetSymbolAddress((void**)&sc,   g_scale);
        cudaGetSymbolAddress((void**)&sh,   g_shift);
        init = true;
    }

    zero_k<<<1, 256>>>();
    cnorm_k<<<2, 256>>>(cb);

    // encoder
    conv_s2_k<1,16,128,128,false><<<dim3(64, NB), 256>>>(x, enc_w1, enc_b1, nullptr, nullptr,
                                                          buf1, sum + 0, sq + 0);
    bnfin_k<<<1, 16>>>(sum + 0,  sq + 0,  enc_g1, enc_be1, sc + 0,  sh + 0,  1048576.f);
    conv_s2_k<16,16,64,64,true><<<dim3(16, NB), 256>>>(buf1, enc_w2, enc_b2, sc + 0, sh + 0,
                                                        buf2, sum + 32, sq + 32);
    bnfin_k<<<1, 16>>>(sum + 32, sq + 32, enc_g2, enc_be2, sc + 32, sh + 32, 262144.f);
    conv_s2_k<16,32,32,32,true><<<dim3(4, NB), 256>>>(buf2, enc_w3, enc_b3, sc + 32, sh + 32,
                                                       buf3, sum + 64, sq + 64);
    bnfin_k<<<1, 32>>>(sum + 64, sq + 64, enc_g3, enc_be3, sc + 64, sh + 64, 65536.f);

    // quantizer (applies BN3+ReLU to get q_in, writes q_out + indices + quant SSE)
    quant_k<<<1024, 256>>>(buf3, cb, buf4, o_idx, sc + 64, sh + 64);

    // decoder
    convT_k<32,16,64,64,false><<<dim3(16, NB), 256>>>(buf4, dec_w1, dec_b1, nullptr, nullptr,
                                                       buf5, sum + 96, sq + 96);
    bnfin_k<<<1, 16>>>(sum + 96,  sq + 96,  dec_g1, dec_be1, sc + 96,  sh + 96,  262144.f);
    convT_k<16,16,128,128,true><<<dim3(64, NB), 256>>>(buf5, dec_w2, dec_b2, sc + 96, sh + 96,
                                                        buf6, sum + 128, sq + 128);
    bnfin_k<<<1, 16>>>(sum + 128, sq + 128, dec_g2, dec_be2, sc + 128, sh + 128, 1048576.f);
    convT_k<16,1,256,256,true><<<dim3(256, NB), 256>>>(buf6, dec_w3, dec_b3, sc + 128, sh + 128,
                                                        buf7, sum + 160, sq + 160);
    bnfin_k<<<1, 1>>>(sum + 160, sq + 160, dec_g3, dec_be3, sc + 160, sh + 160, 4194304.f);

    // output + losses
    final_k<<<16384, 256>>>(x, o, sc + 160, sh + 160);
    loss_k<<<1, 1>>>(o_loss);
}

// round 2
// speedup vs baseline: 2.0798x; 2.0798x over previous
#include <cuda_runtime.h>

// ---------------- scratch (device globals; no allocation allowed) ----------------
#define NB 64
__device__ float g_buf1[NB*16*128*128]; // enc conv1 out (pre-BN)
__device__ float g_buf2[NB*16*64*64];   // enc conv2 out
__device__ float g_buf3[NB*32*32*32];   // enc conv3 out (q_in pre-BN)
__device__ float g_buf4[NB*32*32*32];   // q_out
__device__ float g_buf5[NB*16*64*64];   // dec convT1 out
__device__ float g_buf6[NB*16*128*128]; // dec convT2 out
__device__ float g_buf7[NB*256*256];    // dec convT3 out (pre-BN)
__device__ float g_sum[6*32];
__device__ float g_sq[6*32];
__device__ float g_scale[6*32];
__device__ float g_shift[6*32];
__device__ float g_cnorm[512];
__device__ float g_loss[2];   // [0]=quant SSE, [1]=recon SSE

__device__ __forceinline__ float warp_red(float v) {
    #pragma unroll
    for (int o = 16; o; o >>= 1) v += __shfl_down_sync(0xffffffffu, v, o);
    return v;
}

// ---------------- tiny helpers ----------------
__global__ void zero_k() {
    int i = threadIdx.x;
    if (i < 192) { g_sum[i] = 0.f; g_sq[i] = 0.f; }
    if (i < 2) g_loss[i] = 0.f;
}

__global__ void cnorm_k(const float* __restrict__ cb) {
    int k = blockIdx.x * blockDim.x + threadIdx.x;
    if (k < 512) {
        float s = 0.f;
        #pragma unroll
        for (int c = 0; c < 32; c++) { float v = cb[k*32 + c]; s = fmaf(v, v, s); }
        g_cnorm[k] = s;
    }
}

__global__ void bnfin_k(const float* __restrict__ sum_, const float* __restrict__ sq_,
                        const float* __restrict__ g, const float* __restrict__ be,
                        float* __restrict__ sc, float* __restrict__ sh, float cnt) {
    int c = threadIdx.x;
    float m = sum_[c] / cnt;
    float var = sq_[c] / cnt - m * m;
    float s = g[c] * rsqrtf(var + 1e-5f);
    sc[c] = s;
    sh[c] = be[c] - m * s;
}

// ---------------- strided conv (k=4,s=2,p=1), PY x PX output pixels per thread ----------------
template<int CIN, int COUT, int HO, int WO, int PY, int PX, bool PRE>
__global__ void conv_s2_k(const float* __restrict__ in, const float* __restrict__ w,
                          const float* __restrict__ bias,
                          const float* __restrict__ psc, const float* __restrict__ psh,
                          float* __restrict__ out,
                          float* __restrict__ gsum, float* __restrict__ gsq) {
    constexpr int HI = HO * 2, WI = WO * 2;
    constexpr int QH = HO / PY, QW = WO / PX;
    constexpr int PR = 2 * PY + 2, PC = 2 * PX + 2;
    constexpr int NPIX = PY * PX;
    static_assert((QH * QW) % 128 == 0, "grid divisibility");
    __shared__ float ws[CIN * 16 * COUT];   // [ic][ky*4+kx][oc]
    __shared__ float ssum[COUT], ssq[COUT];
    int tid = threadIdx.x;
    for (int i = tid; i < CIN * 16 * COUT; i += blockDim.x) {
        int oc = i % COUT; int r = i / COUT; int k = r & 15; int ic = r >> 4;
        ws[i] = w[(oc * CIN + ic) * 16 + k];
    }
    if (tid < COUT) { ssum[tid] = 0.f; ssq[tid] = 0.f; }
    __syncthreads();

    int b = blockIdx.y;
    int q = blockIdx.x * blockDim.x + tid;
    int qy = q / QW, qx = q % QW;
    int OY = qy * PY, OX = qx * PX;

    float acc[NPIX][COUT];
    #pragma unroll
    for (int p = 0; p < NPIX; p++)
        #pragma unroll
        for (int oc = 0; oc < COUT; oc++) acc[p][oc] = 0.f;

    const float* inb = in + (size_t)b * CIN * HI * WI;
    #pragma unroll 1
    for (int ic = 0; ic < CIN; ic++) {
        const float* ip = inb + (size_t)ic * HI * WI;
        float sc = 1.f, sh = 0.f;
        if constexpr (PRE) { sc = psc[ic]; sh = psh[ic]; }
        float p[PR][PC];
        #pragma unroll
        for (int r = 0; r < PR; r++) {
            int iy = 2 * OY - 1 + r;
            bool yok = (unsigned)iy < (unsigned)HI;
            const float* rp = ip + (size_t)iy * WI;
            #pragma unroll
            for (int c = 0; c < PC; c++) {
                int ix = 2 * OX - 1 + c;
                float v = 0.f;
                if (yok && (unsigned)ix < (unsigned)WI) {
                    v = rp[ix];
                    if constexpr (PRE) v = fmaxf(fmaf(v, sc, sh), 0.f);
                }
                p[r][c] = v;
            }
        }
        #pragma unroll
        for (int ky = 0; ky < 4; ky++) {
            #pragma unroll
            for (int kx = 0; kx < 4; kx++) {
                const float* wr = &ws[(ic * 16 + ky * 4 + kx) * COUT];
                #pragma unroll
                for (int j = 0; j < COUT / 4; j++) {
                    float4 ww = *(const float4*)(wr + 4 * j);
                    #pragma unroll
                    for (int dy = 0; dy < PY; dy++) {
                        #pragma unroll
                        for (int dx = 0; dx < PX; dx++) {
                            float v = p[2 * dy + ky][2 * dx + kx];
                            int pi = dy * PX + dx;
                            acc[pi][4*j+0] = fmaf(v, ww.x, acc[pi][4*j+0]);
                            acc[pi][4*j+1] = fmaf(v, ww.y, acc[pi][4*j+1]);
                            acc[pi][4*j+2] = fmaf(v, ww.z, acc[pi][4*j+2]);
                            acc[pi][4*j+3] = fmaf(v, ww.w, acc[pi][4*j+3]);
                        }
                    }
                }
            }
        }
    }

    float* ob = out + ((size_t)b * COUT) * HO * WO;
    #pragma unroll
    for (int oc = 0; oc < COUT; oc++) {
        float bz = bias[oc];
        #pragma unroll
        for (int dy = 0; dy < PY; dy++) {
            #pragma unroll
            for (int dx = 0; dx < PX; dx++) {
                int pi = dy * PX + dx;
                float v = acc[pi][oc] + bz;
                acc[pi][oc] = v;
                ob[(size_t)oc * HO * WO + (size_t)(OY + dy) * WO + OX + dx] = v;
            }
        }
    }

    int lane = tid & 31;
    #pragma unroll
    for (int oc = 0; oc < COUT; oc++) {
        float s = 0.f, qs = 0.f;
        #pragma unroll
        for (int p = 0; p < NPIX; p++) { float v = acc[p][oc]; s += v; qs = fmaf(v, v, qs); }
        s = warp_red(s); qs = warp_red(qs);
        if (lane == 0) { atomicAdd(&ssum[oc], s); atomicAdd(&ssq[oc], qs); }
    }
    __syncthreads();
    if (tid < COUT) { atomicAdd(&gsum[tid], ssum[tid]); atomicAdd(&gsq[tid], ssq[tid]); }
}

// ---------------- transposed conv (k=4,s=2,p=1), PY x PX outputs per thread (PY,PX even) ----------------
template<int CIN, int COUT, int HO, int WO, int PY, int PX, bool PRE>
__global__ void convT_k(const float* __restrict__ in, const float* __restrict__ w,
                        const float* __restrict__ bias,
                        const float* __restrict__ psc, const float* __restrict__ psh,
                        float* __restrict__ out,
                        float* __restrict__ gsum, float* __restrict__ gsq) {
    constexpr int HI = HO / 2, WI = WO / 2;
    constexpr int QH = HO / PY, QW = WO / PX;
    constexpr int IR = PY / 2 + 2, ICC = PX / 2 + 2;
    constexpr int NPIX = PY * PX;
    static_assert((QH * QW) % 128 == 0, "grid divisibility");
    __shared__ float ws[CIN * 16 * COUT];   // [ic][ky*4+kx][oc]
    __shared__ float ssum[COUT], ssq[COUT];
    int tid = threadIdx.x;
    for (int i = tid; i < CIN * 16 * COUT; i += blockDim.x) {
        int oc = i % COUT; int r = i / COUT; int k = r & 15; int ic = r >> 4;
        ws[i] = w[(ic * COUT + oc) * 16 + k];   // torch layout [in][out][kh][kw]
    }
    if (tid < COUT) { ssum[tid] = 0.f; ssq[tid] = 0.f; }
    __syncthreads();

    int b = blockIdx.y;
    int q = blockIdx.x * blockDim.x + tid;
    int qy = q / QW, qx = q % QW;
    int OY = qy * PY, OX = qx * PX;
    int Y = OY / 2, X = OX / 2;

    float acc[NPIX][COUT];
    #pragma unroll
    for (int p = 0; p < NPIX; p++)
        #pragma unroll
        for (int oc = 0; oc < COUT; oc++) acc[p][oc] = 0.f;

    const float* inb = in + (size_t)b * CIN * HI * WI;
    #pragma unroll 1
    for (int ic = 0; ic < CIN; ic++) {
        const float* ip = inb + (size_t)ic * HI * WI;
        float sc = 1.f, sh = 0.f;
        if constexpr (PRE) { sc = psc[ic]; sh = psh[ic]; }
        float p[IR][ICC];
        #pragma unroll
        for (int r = 0; r < IR; r++) {
            int iy = Y - 1 + r;
            bool yok = (unsigned)iy < (unsigned)HI;
            const float* rp = ip + (size_t)iy * WI;
            #pragma unroll
            for (int c = 0; c < ICC; c++) {
                int ix = X - 1 + c;
                float v = 0.f;
                if (yok && (unsigned)ix < (unsigned)WI) {
                    v = rp[ix];
                    if constexpr (PRE) v = fmaxf(fmaf(v, sc, sh), 0.f);
                }
                p[r][c] = v;
            }
        }
        #pragma unroll
        for (int ky = 0; ky < 4; ky++) {
            #pragma unroll
            for (int kx = 0; kx < 4; kx++) {
                const float* wr = &ws[(ic * 16 + ky * 4 + kx) * COUT];
                if constexpr (COUT % 4 == 0) {
                    #pragma unroll
                    for (int j = 0; j < COUT / 4; j++) {
                        float4 ww = *(const float4*)(wr + 4 * j);
                        #pragma unroll
                        for (int dy = 1 - (ky & 1); dy < PY; dy += 2) {
                            int r = ((dy + 1 - ky) >> 1) + 1;
                            #pragma unroll
                            for (int dx = 1 - (kx & 1); dx < PX; dx += 2) {
                                int c = ((dx + 1 - kx) >> 1) + 1;
                                float v = p[r][c];
                                int pi = dy * PX + dx;
                                acc[pi][4*j+0] = fmaf(v, ww.x, acc[pi][4*j+0]);
                                acc[pi][4*j+1] = fmaf(v, ww.y, acc[pi][4*j+1]);
                                acc[pi][4*j+2] = fmaf(v, ww.z, acc[pi][4*j+2]);
                                acc[pi][4*j+3] = fmaf(v, ww.w, acc[pi][4*j+3]);
                            }
                        }
                    }
                } else {
                    #pragma unroll
                    for (int oc = 0; oc < COUT; oc++) {
                        float wv = wr[oc];
                        #pragma unroll
                        for (int dy = 1 - (ky & 1); dy < PY; dy += 2) {
                            int r = ((dy + 1 - ky) >> 1) + 1;
                            #pragma unroll
                            for (int dx = 1 - (kx & 1); dx < PX; dx += 2) {
                                int c = ((dx + 1 - kx) >> 1) + 1;
                                acc[dy * PX + dx][oc] = fmaf(p[r][c], wv, acc[dy * PX + dx][oc]);
                            }
                        }
                    }
                }
            }
        }
    }

    float* ob = out + ((size_t)b * COUT) * HO * WO;
    #pragma unroll
    for (int oc = 0; oc < COUT; oc++) {
        float bz = bias[oc];
        #pragma unroll
        for (int dy = 0; dy < PY; dy++) {
            #pragma unroll
            for (int dx = 0; dx < PX; dx++) {
                int pi = dy * PX + dx;
                float v = acc[pi][oc] + bz;
                acc[pi][oc] = v;
                ob[(size_t)oc * HO * WO + (size_t)(OY + dy) * WO + OX + dx] = v;
            }
        }
    }

    int lane = tid & 31;
    #pragma unroll
    for (int oc = 0; oc < COUT; oc++) {
        float s = 0.f, qs = 0.f;
        #pragma unroll
        for (int p = 0; p < NPIX; p++) { float v = acc[p][oc]; s += v; qs = fmaf(v, v, qs); }
        s = warp_red(s); qs = warp_red(qs);
        if (lane == 0) { atomicAdd(&ssum[oc], s); atomicAdd(&ssq[oc], qs); }
    }
    __syncthreads();
    if (tid < COUT) { atomicAdd(&gsum[tid], ssum[tid]); atomicAdd(&gsq[tid], ssq[tid]); }
}

// ---------------- quantizer: 1 thread per vector, codebook tiled through shared ----------------
__global__ void quant_k(const float* __restrict__ q_raw, const float* __restrict__ cb,
                        float* __restrict__ qout, float* __restrict__ idx_out,
                        const float* __restrict__ sc_, const float* __restrict__ sh_) {
    __shared__ float cbs[128 * 32];
    __shared__ float cns[128];
    int tid = threadIdx.x;
    int vec = blockIdx.x * 256 + tid;
    int b = vec >> 10, hw = vec & 1023;

    const float* base = q_raw + ((size_t)b * 32) * 1024 + hw;
    float z[32];
    #pragma unroll
    for (int c = 0; c < 32; c++) {
        float v = base[(size_t)c * 1024];
        z[c] = fmaxf(fmaf(v, sc_[c], sh_[c]), 0.f);   // BN+ReLU -> q_in
    }

    float best = 3.4e38f; int bi = 0;
    #pragma unroll 1
    for (int t = 0; t < 4; t++) {
        __syncthreads();
        // load 128 codes (4096 floats = 1024 float4) cooperatively
        const float4* src = (const float4*)(cb + (size_t)t * 128 * 32);
        float4* dst = (float4*)cbs;
        #pragma unroll
        for (int j = 0; j < 4; j++) dst[tid + 256 * j] = src[tid + 256 * j];
        if (tid < 128) cns[tid] = g_cnorm[t * 128 + tid];
        __syncthreads();
        #pragma unroll 1
        for (int k = 0; k < 128; k++) {
            const float4* cp = (const float4*)(cbs + k * 32);
            float d0 = 0.f, d1 = 0.f, d2 = 0.f, d3 = 0.f;
            #pragma unroll
            for (int j = 0; j < 8; j++) {
                float4 c4 = cp[j];
                d0 = fmaf(z[4*j+0], c4.x, d0);
                d1 = fmaf(z[4*j+1], c4.y, d1);
                d2 = fmaf(z[4*j+2], c4.z, d2);
                d3 = fmaf(z[4*j+3], c4.w, d3);
            }
            float s = cns[k] - 2.f * ((d0 + d1) + (d2 + d3));
            if (s < best) { best = s; bi = t * 128 + k; }
        }
    }

    idx_out[vec] = (float)bi;
    float* qb = qout + ((size_t)b * 32) * 1024 + hw;
    const float4* cbest = (const float4*)(cb + (size_t)bi * 32);
    float sse = 0.f;
    #pragma unroll
    for (int j = 0; j < 8; j++) {
        float4 c4 = __ldg(&cbest[j]);
        float q0 = c4.x, q1 = c4.y, q2 = c4.z, q3 = c4.w;
        qb[(size_t)(4*j+0) * 1024] = q0;
        qb[(size_t)(4*j+1) * 1024] = q1;
        qb[(size_t)(4*j+2) * 1024] = q2;
        qb[(size_t)(4*j+3) * 1024] = q3;
        float e0 = q0 - z[4*j+0], e1 = q1 - z[4*j+1];
        float e2 = q2 - z[4*j+2], e3 = q3 - z[4*j+3];
        sse = fmaf(e0, e0, fmaf(e1, e1, fmaf(e2, e2, fmaf(e3, e3, sse))));
    }
    sse = warp_red(sse);
    if ((tid & 31) == 0) atomicAdd(&g_loss[0], sse);
}

// ---------------- final: BN6-apply, write output, recon SSE ----------------
__global__ void final_k(const float* __restrict__ x, float* __restrict__ dout,
                        const float* __restrict__ sc_, const float* __restrict__ sh_) {
    __shared__ float wsum[8];
    int i = blockIdx.x * blockDim.x + threadIdx.x;
    float sc = sc_[0], sh = sh_[0];
    float y = fmaf(g_buf7[i], sc, sh);
    dout[i] = y;
    float d = x[i] - y;
    float s = d * d;
    s = warp_red(s);
    if ((threadIdx.x & 31) == 0) wsum[threadIdx.x >> 5] = s;
    __syncthreads();
    if (threadIdx.x == 0) {
        float t = 0.f;
        #pragma unroll
        for (int j = 0; j < 8; j++) t += wsum[j];
        atomicAdd(&g_loss[1], t);
    }
}

__global__ void loss_k(float* __restrict__ dloss) {
    dloss[0] = 1.2f * g_loss[0] * (1.f / 2097152.f) + g_loss[1] * (1.f / 4194304.f);
}

// ---------------- launcher ----------------
extern "C" void kernel_launch(void* const* d_in, const int* in_sizes, int n_in,
                              void* d_out, int out_size) {
    const float* x      = (const float*)d_in[0];
    const float* enc_w1 = (const float*)d_in[1];
    const float* enc_b1 = (const float*)d_in[2];
    const float* enc_w2 = (const float*)d_in[3];
    const float* enc_b2 = (const float*)d_in[4];
    const float* enc_w3 = (const float*)d_in[5];
    const float* enc_b3 = (const float*)d_in[6];
    const float* enc_g1 = (const float*)d_in[7];
    const float* enc_be1= (const float*)d_in[8];
    const float* enc_g2 = (const float*)d_in[9];
    const float* enc_be2= (const float*)d_in[10];
    const float* enc_g3 = (const float*)d_in[11];
    const float* enc_be3= (const float*)d_in[12];
    const float* cb     = (const float*)d_in[13];
    const float* dec_w1 = (const float*)d_in[14];
    const float* dec_b1 = (const float*)d_in[15];
    const float* dec_w2 = (const float*)d_in[16];
    const float* dec_b2 = (const float*)d_in[17];
    const float* dec_w3 = (const float*)d_in[18];
    const float* dec_b3 = (const float*)d_in[19];
    const float* dec_g1 = (const float*)d_in[20];
    const float* dec_be1= (const float*)d_in[21];
    const float* dec_g2 = (const float*)d_in[22];
    const float* dec_be2= (const float*)d_in[23];
    const float* dec_g3 = (const float*)d_in[24];
    const float* dec_be3= (const float*)d_in[25];

    float* o = (float*)d_out;
    float* o_loss = o + 4194304;
    float* o_idx  = o + 4194305;

    static float *buf1,*buf2,*buf3,*buf4,*buf5,*buf6,*buf7,*sum,*sq,*sc,*sh;
    static bool init = false;
    if (!init) {
        cudaGetSymbolAddress((void**)&buf1, g_buf1);
        cudaGetSymbolAddress((void**)&buf2, g_buf2);
        cudaGetSymbolAddress((void**)&buf3, g_buf3);
        cudaGetSymbolAddress((void**)&buf4, g_buf4);
        cudaGetSymbolAddress((void**)&buf5, g_buf5);
        cudaGetSymbolAddress((void**)&buf6, g_buf6);
        cudaGetSymbolAddress((void**)&buf7, g_buf7);
        cudaGetSymbolAddress((void**)&sum,  g_sum);
        cudaGetSymbolAddress((void**)&sq,   g_sq);
        cudaGetSymbolAddress((void**)&sc,   g_scale);
        cudaGetSymbolAddress((void**)&sh,   g_shift);
        init = true;
    }

    zero_k<<<1, 256>>>();
    cnorm_k<<<2, 256>>>(cb);

    // encoder
    conv_s2_k<1,16,128,128,2,2,false><<<dim3(64*64/128, NB), 128>>>(x, enc_w1, enc_b1, nullptr, nullptr,
                                                          buf1, sum + 0, sq + 0);
    bnfin_k<<<1, 16>>>(sum + 0,  sq + 0,  enc_g1, enc_be1, sc + 0,  sh + 0,  1048576.f);
    conv_s2_k<16,16,64,64,2,2,true><<<dim3(32*32/128, NB), 128>>>(buf1, enc_w2, enc_b2, sc + 0, sh + 0,
                                                        buf2, sum + 32, sq + 32);
    bnfin_k<<<1, 16>>>(sum + 32, sq + 32, enc_g2, enc_be2, sc + 32, sh + 32, 262144.f);
    conv_s2_k<16,32,32,32,1,2,true><<<dim3(32*16/128, NB), 128>>>(buf2, enc_w3, enc_b3, sc + 32, sh + 32,
                                                       buf3, sum + 64, sq + 64);
    bnfin_k<<<1, 32>>>(sum + 64, sq + 64, enc_g3, enc_be3, sc + 64, sh + 64, 65536.f);

    // quantizer (applies BN3+ReLU to get q_in, writes q_out + indices + quant SSE)
    quant_k<<<256, 256>>>(buf3, cb, buf4, o_idx, sc + 64, sh + 64);

    // decoder
    convT_k<32,16,64,64,2,2,false><<<dim3(32*32/128, NB), 128>>>(buf4, dec_w1, dec_b1, nullptr, nullptr,
                                                       buf5, sum + 96, sq + 96);
    bnfin_k<<<1, 16>>>(sum + 96,  sq + 96,  dec_g1, dec_be1, sc + 96,  sh + 96,  262144.f);
    convT_k<16,16,128,128,2,2,true><<<dim3(64*64/128, NB), 128>>>(buf5, dec_w2, dec_b2, sc + 96, sh + 96,
                                                        buf6, sum + 128, sq + 128);
    bnfin_k<<<1, 16>>>(sum + 128, sq + 128, dec_g2, dec_be2, sc + 128, sh + 128, 1048576.f);
    convT_k<16,1,256,256,4,4,true><<<dim3(64*64/128, NB), 128>>>(buf6, dec_w3, dec_b3, sc + 128, sh + 128,
                                                        buf7, sum + 160, sq + 160);
    bnfin_k<<<1, 1>>>(sum + 160, sq + 160, dec_g3, dec_be3, sc + 160, sh + 160, 4194304.f);

    // output + losses
    final_k<<<16384, 256>>>(x, o, sc + 160, sh + 160);
    loss_k<<<1, 1>>>(o_loss);
}

// round 3
// speedup vs baseline: 2.3279x; 1.1193x over previous
#include <cuda_runtime.h>

// ---------------- scratch (device globals; no allocation allowed) ----------------
#define NB 64
__device__ float g_buf1[NB*16*128*128]; // enc conv1 out (pre-BN)
__device__ float g_buf2[NB*16*64*64];   // enc conv2 out
__device__ float g_buf3[NB*32*32*32];   // enc conv3 out (q_in pre-BN)
__device__ float g_buf4[NB*32*32*32];   // q_out
__device__ float g_buf5[NB*16*64*64];   // dec convT1 out
__device__ float g_buf6[NB*16*128*128]; // dec convT2 out
__device__ float g_buf7[NB*256*256];    // dec convT3 out (pre-BN)
__device__ float g_sum[6*32];
__device__ float g_sq[6*32];
__device__ float g_cnorm[512];
__device__ float g_loss[2];   // [0]=quant SSE, [1]=recon SSE

typedef unsigned long long ull;

__device__ __forceinline__ float warp_red(float v) {
    #pragma unroll
    for (int o = 16; o; o >>= 1) v += __shfl_down_sync(0xffffffffu, v, o);
    return v;
}

// ---------------- packed f32x2 helpers (SASS FFMA2 — ptxas never emits this from C++) ----
__device__ __forceinline__ ull pk2(float lo, float hi) {
    ull r; asm("mov.b64 %0, {%1, %2};" : "=l"(r) : "f"(lo), "f"(hi)); return r;
}
__device__ __forceinline__ void upk2(ull v, float& lo, float& hi) {
    asm("mov.b64 {%0, %1}, %2;" : "=f"(lo), "=f"(hi) : "l"(v));
}
__device__ __forceinline__ ull fma2(ull a, ull b, ull c) {
    ull d; asm("fma.rn.f32x2 %0, %1, %2, %3;" : "=l"(d) : "l"(a), "l"(b), "l"(c)); return d;
}

// ---------------- tiny helpers ----------------
__global__ void zero_k() {
    int i = threadIdx.x;
    if (i < 192) { g_sum[i] = 0.f; g_sq[i] = 0.f; }
    if (i < 2) g_loss[i] = 0.f;
}

__global__ void cnorm_k(const float* __restrict__ cb) {
    int k = blockIdx.x * blockDim.x + threadIdx.x;
    if (k < 512) {
        float s = 0.f;
        #pragma unroll
        for (int c = 0; c < 32; c++) { float v = cb[k*32 + c]; s = fmaf(v, v, s); }
        g_cnorm[k] = s;
    }
}

// per-block BN finalize into shared
template<int C>
__device__ __forceinline__ void bn_block(const float* __restrict__ gsum_in,
                                         const float* __restrict__ gsq_in,
                                         const float* __restrict__ gam,
                                         const float* __restrict__ bet,
                                         float cnt, float* ssc, float* ssh, int tid) {
    if (tid < C) {
        float m = gsum_in[tid] / cnt;
        float var = gsq_in[tid] / cnt - m * m;
        float s = gam[tid] * rsqrtf(var + 1e-5f);
        ssc[tid] = s;
        ssh[tid] = bet[tid] - m * s;
    }
}

// ---------------- strided conv (k=4,s=2,p=1), PY x PX output pixels per thread, packed FFMA2 ----
template<int CIN, int COUT, int HO, int WO, int PY, int PX, bool PRE>
__global__ void conv_s2_k(const float* __restrict__ in, const float* __restrict__ w,
                          const float* __restrict__ bias,
                          const float* __restrict__ gsum_in, const float* __restrict__ gsq_in,
                          const float* __restrict__ gam, const float* __restrict__ bet, float cnt,
                          float* __restrict__ out,
                          float* __restrict__ gsum, float* __restrict__ gsq) {
    constexpr int HI = HO * 2, WI = WO * 2;
    constexpr int QH = HO / PY, QW = WO / PX;
    constexpr int PR = 2 * PY + 2, PC = 2 * PX + 2;
    constexpr int NPIX = PY * PX;
    static_assert(COUT % 4 == 0, "packed path needs COUT%4==0");
    __shared__ float ws[CIN * 16 * COUT];   // [ic][ky*4+kx][oc]
    __shared__ float ssum[COUT], ssq[COUT];
    __shared__ float ssc[CIN], ssh[CIN];
    int tid = threadIdx.x;
    for (int i = tid; i < CIN * 16 * COUT; i += blockDim.x) {
        int oc = i % COUT; int r = i / COUT; int k = r & 15; int ic = r >> 4;
        ws[i] = w[(oc * CIN + ic) * 16 + k];
    }
    if (tid < COUT) { ssum[tid] = 0.f; ssq[tid] = 0.f; }
    if constexpr (PRE) bn_block<CIN>(gsum_in, gsq_in, gam, bet, cnt, ssc, ssh, tid);
    __syncthreads();

    int b = blockIdx.y;
    int q = blockIdx.x * blockDim.x + tid;
    int qy = q / QW, qx = q % QW;
    int OY = qy * PY, OX = qx * PX;

    ull acc2[NPIX][COUT / 2];
    #pragma unroll
    for (int p = 0; p < NPIX; p++)
        #pragma unroll
        for (int j = 0; j < COUT / 2; j++) acc2[p][j] = 0ull;

    const float* inb = in + (size_t)b * CIN * HI * WI;
    #pragma unroll 1
    for (int ic = 0; ic < CIN; ic++) {
        const float* ip = inb + (size_t)ic * HI * WI;
        float sc = 1.f, sh = 0.f;
        if constexpr (PRE) { sc = ssc[ic]; sh = ssh[ic]; }
        float p[PR][PC];
        #pragma unroll
        for (int r = 0; r < PR; r++) {
            int iy = 2 * OY - 1 + r;
            bool yok = (unsigned)iy < (unsigned)HI;
            const float* rp = ip + (size_t)iy * WI;
            #pragma unroll
            for (int c = 0; c < PC; c++) {
                int ix = 2 * OX - 1 + c;
                float v = 0.f;
                if (yok && (unsigned)ix < (unsigned)WI) {
                    v = rp[ix];
                    if constexpr (PRE) v = fmaxf(fmaf(v, sc, sh), 0.f);
                }
                p[r][c] = v;
            }
        }
        #pragma unroll
        for (int ky = 0; ky < 4; ky++) {
            #pragma unroll
            for (int kx = 0; kx < 4; kx++) {
                const ulonglong2* w4 = (const ulonglong2*)&ws[(ic * 16 + ky * 4 + kx) * COUT];
                ull w2[COUT / 2];
                #pragma unroll
                for (int jj = 0; jj < COUT / 4; jj++) {
                    ulonglong2 ww = w4[jj];
                    w2[2 * jj] = ww.x; w2[2 * jj + 1] = ww.y;
                }
                #pragma unroll
                for (int dy = 0; dy < PY; dy++) {
                    #pragma unroll
                    for (int dx = 0; dx < PX; dx++) {
                        float v = p[2 * dy + ky][2 * dx + kx];
                        ull v2 = pk2(v, v);
                        int pi = dy * PX + dx;
                        #pragma unroll
                        for (int j = 0; j < COUT / 2; j++)
                            acc2[pi][j] = fma2(v2, w2[j], acc2[pi][j]);
                    }
                }
            }
        }
    }

    float acc[NPIX][COUT];
    #pragma unroll
    for (int p = 0; p < NPIX; p++)
        #pragma unroll
        for (int j = 0; j < COUT / 2; j++) upk2(acc2[p][j], acc[p][2*j], acc[p][2*j+1]);

    float* ob = out + ((size_t)b * COUT) * HO * WO;
    #pragma unroll
    for (int oc = 0; oc < COUT; oc++) {
        float bz = bias[oc];
        #pragma unroll
        for (int dy = 0; dy < PY; dy++) {
            #pragma unroll
            for (int dx = 0; dx < PX; dx++) {
                int pi = dy * PX + dx;
                float v = acc[pi][oc] + bz;
                acc[pi][oc] = v;
                ob[(size_t)oc * HO * WO + (size_t)(OY + dy) * WO + OX + dx] = v;
            }
        }
    }

    int lane = tid & 31;
    #pragma unroll
    for (int oc = 0; oc < COUT; oc++) {
        float s = 0.f, qs = 0.f;
        #pragma unroll
        for (int p = 0; p < NPIX; p++) { float v = acc[p][oc]; s += v; qs = fmaf(v, v, qs); }
        s = warp_red(s); qs = warp_red(qs);
        if (lane == 0) { atomicAdd(&ssum[oc], s); atomicAdd(&ssq[oc], qs); }
    }
    __syncthreads();
    if (tid < COUT) { atomicAdd(&gsum[tid], ssum[tid]); atomicAdd(&gsq[tid], ssq[tid]); }
}

// ---------------- transposed conv (k=4,s=2,p=1), PY x PX outputs per thread ----------------
template<int CIN, int COUT, int HO, int WO, int PY, int PX, bool PRE>
__global__ void convT_k(const float* __restrict__ in, const float* __restrict__ w,
                        const float* __restrict__ bias,
                        const float* __restrict__ gsum_in, const float* __restrict__ gsq_in,
                        const float* __restrict__ gam, const float* __restrict__ bet, float cnt,
                        float* __restrict__ out,
                        float* __restrict__ gsum, float* __restrict__ gsq) {
    constexpr int HI = HO / 2, WI = WO / 2;
    constexpr int QH = HO / PY, QW = WO / PX;
    constexpr int IR = PY / 2 + 2, ICC = PX / 2 + 2;
    constexpr int NPIX = PY * PX;
    __shared__ float ws[CIN * 16 * COUT];   // [ic][ky*4+kx][oc]
    __shared__ float ssum[COUT], ssq[COUT];
    __shared__ float ssc[CIN], ssh[CIN];
    int tid = threadIdx.x;
    for (int i = tid; i < CIN * 16 * COUT; i += blockDim.x) {
        int oc = i % COUT; int r = i / COUT; int k = r & 15; int ic = r >> 4;
        ws[i] = w[(ic * COUT + oc) * 16 + k];   // torch layout [in][out][kh][kw]
    }
    if (tid < COUT) { ssum[tid] = 0.f; ssq[tid] = 0.f; }
    if constexpr (PRE) bn_block<CIN>(gsum_in, gsq_in, gam, bet, cnt, ssc, ssh, tid);
    __syncthreads();

    int b = blockIdx.y;
    int q = blockIdx.x * blockDim.x + tid;
    int qy = q / QW, qx = q % QW;
    int OY = qy * PY, OX = qx * PX;
    int Y = OY / 2, X = OX / 2;

    float acc[NPIX][COUT];
    ull acc2[NPIX][(COUT % 4 == 0) ? COUT / 2 : 1];
    if constexpr (COUT % 4 == 0) {
        #pragma unroll
        for (int p = 0; p < NPIX; p++)
            #pragma unroll
            for (int j = 0; j < COUT / 2; j++) acc2[p][j] = 0ull;
    } else {
        #pragma unroll
        for (int p = 0; p < NPIX; p++)
            #pragma unroll
            for (int oc = 0; oc < COUT; oc++) acc[p][oc] = 0.f;
    }

    const float* inb = in + (size_t)b * CIN * HI * WI;
    #pragma unroll 1
    for (int ic = 0; ic < CIN; ic++) {
        const float* ip = inb + (size_t)ic * HI * WI;
        float sc = 1.f, sh = 0.f;
        if constexpr (PRE) { sc = ssc[ic]; sh = ssh[ic]; }
        float p[IR][ICC];
        #pragma unroll
        for (int r = 0; r < IR; r++) {
            int iy = Y - 1 + r;
            bool yok = (unsigned)iy < (unsigned)HI;
            const float* rp = ip + (size_t)iy * WI;
            #pragma unroll
            for (int c = 0; c < ICC; c++) {
                int ix = X - 1 + c;
                float v = 0.f;
                if (yok && (unsigned)ix < (unsigned)WI) {
                    v = rp[ix];
                    if constexpr (PRE) v = fmaxf(fmaf(v, sc, sh), 0.f);
                }
                p[r][c] = v;
            }
        }
        #pragma unroll
        for (int ky = 0; ky < 4; ky++) {
            #pragma unroll
            for (int kx = 0; kx < 4; kx++) {
                const float* wr = &ws[(ic * 16 + ky * 4 + kx) * COUT];
                if constexpr (COUT % 4 == 0) {
                    const ulonglong2* w4 = (const ulonglong2*)wr;
                    ull w2[COUT / 2];
                    #pragma unroll
                    for (int jj = 0; jj < COUT / 4; jj++) {
                        ulonglong2 ww = w4[jj];
                        w2[2 * jj] = ww.x; w2[2 * jj + 1] = ww.y;
                    }
                    #pragma unroll
                    for (int dy = 1 - (ky & 1); dy < PY; dy += 2) {
                        int r = ((dy + 1 - ky) >> 1) + 1;
                        #pragma unroll
                        for (int dx = 1 - (kx & 1); dx < PX; dx += 2) {
                            int c = ((dx + 1 - kx) >> 1) + 1;
                            float v = p[r][c];
                            ull v2 = pk2(v, v);
                            int pi = dy * PX + dx;
                            #pragma unroll
                            for (int j = 0; j < COUT / 2; j++)
                                acc2[pi][j] = fma2(v2, w2[j], acc2[pi][j]);
                        }
                    }
                } else {
                    #pragma unroll
                    for (int oc = 0; oc < COUT; oc++) {
                        float wv = wr[oc];
                        #pragma unroll
                        for (int dy = 1 - (ky & 1); dy < PY; dy += 2) {
                            int r = ((dy + 1 - ky) >> 1) + 1;
                            #pragma unroll
                            for (int dx = 1 - (kx & 1); dx < PX; dx += 2) {
                                int c = ((dx + 1 - kx) >> 1) + 1;
                                acc[dy * PX + dx][oc] = fmaf(p[r][c], wv, acc[dy * PX + dx][oc]);
                            }
                        }
                    }
                }
            }
        }
    }

    if constexpr (COUT % 4 == 0) {
        #pragma unroll
        for (int p = 0; p < NPIX; p++)
            #pragma unroll
            for (int j = 0; j < COUT / 2; j++) upk2(acc2[p][j], acc[p][2*j], acc[p][2*j+1]);
    }

    float* ob = out + ((size_t)b * COUT) * HO * WO;
    #pragma unroll
    for (int oc = 0; oc < COUT; oc++) {
        float bz = bias[oc];
        #pragma unroll
        for (int dy = 0; dy < PY; dy++) {
            #pragma unroll
            for (int dx = 0; dx < PX; dx++) {
                int pi = dy * PX + dx;
                float v = acc[pi][oc] + bz;
                acc[pi][oc] = v;
                ob[(size_t)oc * HO * WO + (size_t)(OY + dy) * WO + OX + dx] = v;
            }
        }
    }

    int lane = tid & 31;
    #pragma unroll
    for (int oc = 0; oc < COUT; oc++) {
        float s = 0.f, qs = 0.f;
        #pragma unroll
        for (int p = 0; p < NPIX; p++) { float v = acc[p][oc]; s += v; qs = fmaf(v, v, qs); }
        s = warp_red(s); qs = warp_red(qs);
        if (lane == 0) { atomicAdd(&ssum[oc], s); atomicAdd(&ssq[oc], qs); }
    }
    __syncthreads();
    if (tid < COUT) { atomicAdd(&gsum[tid], ssum[tid]); atomicAdd(&gsq[tid], ssq[tid]); }
}

// ---------------- quantizer: 1 thread per vector, codebook tiled through shared, packed FFMA2 ----
__global__ void quant_k(const float* __restrict__ q_raw, const float* __restrict__ cb,
                        float* __restrict__ qout, float* __restrict__ idx_out,
                        const float* __restrict__ gsum_in, const float* __restrict__ gsq_in,
                        const float* __restrict__ gam, const float* __restrict__ bet) {
    __shared__ float cbs[128 * 32];
    __shared__ float cns[128];
    __shared__ float ssc[32], ssh[32];
    int tid = threadIdx.x;
    bn_block<32>(gsum_in, gsq_in, gam, bet, 65536.f, ssc, ssh, tid);
    __syncthreads();

    int vec = blockIdx.x * 256 + tid;
    int b = vec >> 10, hw = vec & 1023;

    const float* base = q_raw + ((size_t)b * 32) * 1024 + hw;
    ull z2[16];
    #pragma unroll
    for (int j = 0; j < 16; j++) {
        float v0 = base[(size_t)(2*j)   * 1024];
        float v1 = base[(size_t)(2*j+1) * 1024];
        v0 = fmaxf(fmaf(v0, ssc[2*j],   ssh[2*j]),   0.f);
        v1 = fmaxf(fmaf(v1, ssc[2*j+1], ssh[2*j+1]), 0.f);
        z2[j] = pk2(v0, v1);
    }

    float best = 3.4e38f; int bi = 0;
    #pragma unroll 1
    for (int t = 0; t < 4; t++) {
        __syncthreads();
        const float4* src = (const float4*)(cb + (size_t)t * 128 * 32);
        float4* dst = (float4*)cbs;
        #pragma unroll
        for (int j = 0; j < 4; j++) dst[tid + 256 * j] = src[tid + 256 * j];
        if (tid < 128) cns[tid] = g_cnorm[t * 128 + tid];
        __syncthreads();
        #pragma unroll 1
        for (int k = 0; k < 128; k += 2) {
            const ulonglong2* cp0 = (const ulonglong2*)(cbs + k * 32);
            const ulonglong2* cp1 = (const ulonglong2*)(cbs + (k + 1) * 32);
            ull a0 = 0ull, a1 = 0ull, b0 = 0ull, b1 = 0ull;
            #pragma unroll
            for (int i = 0; i < 8; i++) {
                ulonglong2 c0 = cp0[i];
                ulonglong2 c1 = cp1[i];
                a0 = fma2(z2[2*i],   c0.x, a0);
                a1 = fma2(z2[2*i+1], c0.y, a1);
                b0 = fma2(z2[2*i],   c1.x, b0);
                b1 = fma2(z2[2*i+1], c1.y, b1);
            }
            float x0, x1, x2, x3, y0, y1, y2, y3;
            upk2(a0, x0, x1); upk2(a1, x2, x3);
            upk2(b0, y0, y1); upk2(b1, y2, y3);
            float dot0 = (x0 + x1) + (x2 + x3);
            float dot1 = (y0 + y1) + (y2 + y3);
            float s0 = cns[k]     - 2.f * dot0;
            float s1 = cns[k + 1] - 2.f * dot1;
            if (s0 < best) { best = s0; bi = t * 128 + k; }
            if (s1 < best) { best = s1; bi = t * 128 + k + 1; }
        }
    }

    idx_out[vec] = (float)bi;
    float* qb = qout + ((size_t)b * 32) * 1024 + hw;
    const float4* cbest = (const float4*)(cb + (size_t)bi * 32);
    float sse = 0.f;
    #pragma unroll
    for (int j = 0; j < 8; j++) {
        float4 c4 = __ldg(&cbest[j]);
        float z0, z1, z2f, z3;
        upk2(z2[2*j], z0, z1); upk2(z2[2*j+1], z2f, z3);
        qb[(size_t)(4*j+0) * 1024] = c4.x;
        qb[(size_t)(4*j+1) * 1024] = c4.y;
        qb[(size_t)(4*j+2) * 1024] = c4.z;
        qb[(size_t)(4*j+3) * 1024] = c4.w;
        float e0 = c4.x - z0, e1 = c4.y - z1;
        float e2 = c4.z - z2f, e3 = c4.w - z3;
        sse = fmaf(e0, e0, fmaf(e1, e1, fmaf(e2, e2, fmaf(e3, e3, sse))));
    }
    sse = warp_red(sse);
    if ((tid & 31) == 0) atomicAdd(&g_loss[0], sse);
}

// ---------------- final: BN6-apply (computed in-block), write output, recon SSE ----------------
__global__ void final_k(const float* __restrict__ x, float* __restrict__ dout,
                        const float* __restrict__ gsum_in, const float* __restrict__ gsq_in,
                        const float* __restrict__ gam, const float* __restrict__ bet) {
    __shared__ float wsum[8];
    __shared__ float sbn[2];
    if (threadIdx.x == 0) {
        float m = gsum_in[0] * (1.f / 4194304.f);
        float var = gsq_in[0] * (1.f / 4194304.f) - m * m;
        float s = gam[0] * rsqrtf(var + 1e-5f);
        sbn[0] = s; sbn[1] = bet[0] - m * s;
    }
    __syncthreads();
    int i = blockIdx.x * blockDim.x + threadIdx.x;
    float y = fmaf(g_buf7[i], sbn[0], sbn[1]);
    dout[i] = y;
    float d = x[i] - y;
    float s = d * d;
    s = warp_red(s);
    if ((threadIdx.x & 31) == 0) wsum[threadIdx.x >> 5] = s;
    __syncthreads();
    if (threadIdx.x == 0) {
        float t = 0.f;
        #pragma unroll
        for (int j = 0; j < 8; j++) t += wsum[j];
        atomicAdd(&g_loss[1], t);
    }
}

__global__ void loss_k(float* __restrict__ dloss) {
    dloss[0] = 1.2f * g_loss[0] * (1.f / 2097152.f) + g_loss[1] * (1.f / 4194304.f);
}

// ---------------- launcher ----------------
extern "C" void kernel_launch(void* const* d_in, const int* in_sizes, int n_in,
                              void* d_out, int out_size) {
    const float* x      = (const float*)d_in[0];
    const float* enc_w1 = (const float*)d_in[1];
    const float* enc_b1 = (const float*)d_in[2];
    const float* enc_w2 = (const float*)d_in[3];
    const float* enc_b2 = (const float*)d_in[4];
    const float* enc_w3 = (const float*)d_in[5];
    const float* enc_b3 = (const float*)d_in[6];
    const float* enc_g1 = (const float*)d_in[7];
    const float* enc_be1= (const float*)d_in[8];
    const float* enc_g2 = (const float*)d_in[9];
    const float* enc_be2= (const float*)d_in[10];
    const float* enc_g3 = (const float*)d_in[11];
    const float* enc_be3= (const float*)d_in[12];
    const float* cb     = (const float*)d_in[13];
    const float* dec_w1 = (const float*)d_in[14];
    const float* dec_b1 = (const float*)d_in[15];
    const float* dec_w2 = (const float*)d_in[16];
    const float* dec_b2 = (const float*)d_in[17];
    const float* dec_w3 = (const float*)d_in[18];
    const float* dec_b3 = (const float*)d_in[19];
    const float* dec_g1 = (const float*)d_in[20];
    const float* dec_be1= (const float*)d_in[21];
    const float* dec_g2 = (const float*)d_in[22];
    const float* dec_be2= (const float*)d_in[23];
    const float* dec_g3 = (const float*)d_in[24];
    const float* dec_be3= (const float*)d_in[25];

    float* o = (float*)d_out;
    float* o_loss = o + 4194304;
    float* o_idx  = o + 4194305;

    static float *buf1,*buf2,*buf3,*buf4,*buf5,*buf6,*buf7,*sum,*sq;
    static bool init = false;
    if (!init) {
        cudaGetSymbolAddress((void**)&buf1, g_buf1);
        cudaGetSymbolAddress((void**)&buf2, g_buf2);
        cudaGetSymbolAddress((void**)&buf3, g_buf3);
        cudaGetSymbolAddress((void**)&buf4, g_buf4);
        cudaGetSymbolAddress((void**)&buf5, g_buf5);
        cudaGetSymbolAddress((void**)&buf6, g_buf6);
        cudaGetSymbolAddress((void**)&buf7, g_buf7);
        cudaGetSymbolAddress((void**)&sum,  g_sum);
        cudaGetSymbolAddress((void**)&sq,   g_sq);
        init = true;
    }

    zero_k<<<1, 256>>>();                                         // launch 1
    cnorm_k<<<2, 256>>>(cb);                                      // launch 2

    // encoder (BN of the previous layer computed in-block from g_sum/g_sq)
    conv_s2_k<1,16,128,128,2,2,false><<<dim3(64*64/128, NB), 128>>>(   // launch 3
        x, enc_w1, enc_b1, nullptr, nullptr, nullptr, nullptr, 0.f,
        buf1, sum + 0, sq + 0);
    conv_s2_k<16,16,64,64,2,2,true><<<dim3(32*32/128, NB), 128>>>(     // launch 4
        buf1, enc_w2, enc_b2, sum + 0, sq + 0, enc_g1, enc_be1, 1048576.f,
        buf2, sum + 32, sq + 32);
    conv_s2_k<16,32,32,32,1,2,true><<<dim3(32*16/128, NB), 128>>>(     // launch 5
        buf2, enc_w3, enc_b3, sum + 32, sq + 32, enc_g2, enc_be2, 262144.f,
        buf3, sum + 64, sq + 64);

    // quantizer — launch 6 (this is what ncu -s 5 -c 1 captures)
    quant_k<<<256, 256>>>(buf3, cb, buf4, o_idx, sum + 64, sq + 64, enc_g3, enc_be3);

    // decoder
    convT_k<32,16,64,64,2,2,false><<<dim3(32*32/128, NB), 128>>>(      // launch 7
        buf4, dec_w1, dec_b1, nullptr, nullptr, nullptr, nullptr, 0.f,
        buf5, sum + 96, sq + 96);
    convT_k<16,16,128,128,2,2,true><<<dim3(64*64/128, NB), 128>>>(     // launch 8
        buf5, dec_w2, dec_b2, sum + 96, sq + 96, dec_g1, dec_be1, 262144.f,
        buf6, sum + 128, sq + 128);
    convT_k<16,1,256,256,4,4,true><<<dim3(64*64/128, NB), 128>>>(      // launch 9
        buf6, dec_w3, dec_b3, sum + 128, sq + 128, dec_g2, dec_be2, 1048576.f,
        buf7, sum + 160, sq + 160);

    // output + losses
    final_k<<<16384, 256>>>(x, o, sum + 160, sq + 160, dec_g3, dec_be3);  // launch 10
    loss_k<<<1, 1>>>(o_loss);                                              // launch 11
}

// round 4
// speedup vs baseline: 2.3593x; 1.0135x over previous
#include <cuda_runtime.h>

// ---------------- scratch (device globals; no allocation allowed) ----------------
#define NB 64
__device__ float g_buf1[NB*16*128*128]; // enc conv1 out (pre-BN)
__device__ float g_buf2[NB*16*64*64];   // enc conv2 out
__device__ float g_buf3[NB*32*32*32];   // enc conv3 out (q_in pre-BN)
__device__ float g_buf4[NB*32*32*32];   // q_out
__device__ float g_buf5[NB*16*64*64];   // dec convT1 out
__device__ float g_buf6[NB*16*128*128]; // dec convT2 out
__device__ float g_buf7[NB*256*256];    // dec convT3 out (pre-BN)
__device__ float g_sum[6*32];
__device__ float g_sq[6*32];
__device__ float g_cnorm[512];
__device__ float g_loss[2];   // [0]=quant SSE, [1]=recon SSE

typedef unsigned long long ull;

__device__ __forceinline__ float warp_red(float v) {
    #pragma unroll
    for (int o = 16; o; o >>= 1) v += __shfl_down_sync(0xffffffffu, v, o);
    return v;
}

// ---------------- packed f32x2 helpers ----------------
__device__ __forceinline__ ull pk2(float lo, float hi) {
    ull r; asm("mov.b64 %0, {%1, %2};" : "=l"(r) : "f"(lo), "f"(hi)); return r;
}
__device__ __forceinline__ void upk2(ull v, float& lo, float& hi) {
    asm("mov.b64 {%0, %1}, %2;" : "=f"(lo), "=f"(hi) : "l"(v));
}
__device__ __forceinline__ ull fma2(ull a, ull b, ull c) {
    ull d; asm("fma.rn.f32x2 %0, %1, %2, %3;" : "=l"(d) : "l"(a), "l"(b), "l"(c)); return d;
}

// ---------------- tiny helpers ----------------
__global__ void zero_k() {
    int i = threadIdx.x;
    if (i < 192) { g_sum[i] = 0.f; g_sq[i] = 0.f; }
    if (i < 2) g_loss[i] = 0.f;
}

__global__ void cnorm_k(const float* __restrict__ cb) {
    int k = blockIdx.x * blockDim.x + threadIdx.x;
    if (k < 512) {
        float s = 0.f;
        #pragma unroll
        for (int c = 0; c < 32; c++) { float v = cb[k*32 + c]; s = fmaf(v, v, s); }
        g_cnorm[k] = s;
    }
}

// per-block BN finalize into shared
template<int C>
__device__ __forceinline__ void bn_block(const float* __restrict__ gsum_in,
                                         const float* __restrict__ gsq_in,
                                         const float* __restrict__ gam,
                                         const float* __restrict__ bet,
                                         float cnt, float* ssc, float* ssh, int tid) {
    if (tid < C) {
        float m = gsum_in[tid] / cnt;
        float var = gsq_in[tid] / cnt - m * m;
        float s = gam[tid] * rsqrtf(var + 1e-5f);
        ssc[tid] = s;
        ssh[tid] = bet[tid] - m * s;
    }
}

// ---------------- strided conv (k=4,s=2,p=1), smem-staged input tile ----------------
// Block = 128 threads as 16x8; each thread computes PY x PX outputs.
template<int CIN, int COUT, int HO, int WO, int PY, int PX, bool PRE>
__global__ void conv_s2_k(const float* __restrict__ in, const float* __restrict__ w,
                          const float* __restrict__ bias,
                          const float* __restrict__ gsum_in, const float* __restrict__ gsq_in,
                          const float* __restrict__ gam, const float* __restrict__ bet, float cnt,
                          float* __restrict__ out,
                          float* __restrict__ gsum, float* __restrict__ gsq) {
    constexpr int HI = HO * 2, WI = WO * 2;
    constexpr int TBX = 16, TBY = 8;
    constexpr int HT = TBY * PY, WT = TBX * PX;   // output tile per block
    constexpr int CX = WO / WT, CY = HO / HT;
    constexpr int TROWS = 2 * HT + 2, TCOLS = 2 * WT + 2;
    constexpr int TCS = TCOLS + 1;
    constexpr int NPIX = PY * PX;
    static_assert(COUT % 4 == 0, "packed path");
    __shared__ float ws[CIN * 16 * COUT];   // [ic][ky*4+kx][oc]
    __shared__ float tile[TROWS * TCS];
    __shared__ float ssum[COUT], ssq[COUT];
    __shared__ float ssc[(PRE ? CIN : 1)], ssh[(PRE ? CIN : 1)];
    int tid = threadIdx.x;
    for (int i = tid; i < CIN * 16 * COUT; i += 128) {
        int oc = i % COUT; int r = i / COUT; int k = r & 15; int ic = r >> 4;
        ws[i] = w[(oc * CIN + ic) * 16 + k];
    }
    if (tid < COUT) { ssum[tid] = 0.f; ssq[tid] = 0.f; }
    if constexpr (PRE) bn_block<CIN>(gsum_in, gsq_in, gam, bet, cnt, ssc, ssh, tid);

    int b = blockIdx.y;
    int chX = blockIdx.x % CX, chY = blockIdx.x / CX;
    int gy0 = 2 * (chY * HT) - 1, gx0 = 2 * (chX * WT) - 1;
    int tx = tid % TBX, ty = tid / TBX;
    int OYl = ty * PY, OXl = tx * PX;
    int OY = chY * HT + OYl, OX = chX * WT + OXl;

    ull acc2[NPIX][COUT / 2];
    #pragma unroll
    for (int p = 0; p < NPIX; p++)
        #pragma unroll
        for (int j = 0; j < COUT / 2; j++) acc2[p][j] = 0ull;

    const float* inb = in + (size_t)b * CIN * HI * WI;
    #pragma unroll 1
    for (int ic = 0; ic < CIN; ic++) {
        const float* ip = inb + (size_t)ic * HI * WI;
        __syncthreads();   // previous-iter readers done; also orders ws/ssc on iter 0
        float sc = 1.f, sh = 0.f;
        if constexpr (PRE) { sc = ssc[ic]; sh = ssh[ic]; }
        for (int idx = tid; idx < TROWS * TCOLS; idx += 128) {
            int r = idx / TCOLS, c = idx % TCOLS;
            int gy = gy0 + r, gx = gx0 + c;
            float v = 0.f;
            if ((unsigned)gy < (unsigned)HI && (unsigned)gx < (unsigned)WI) {
                v = ip[(size_t)gy * WI + gx];
                if constexpr (PRE) v = fmaxf(fmaf(v, sc, sh), 0.f);
            }
            tile[r * TCS + c] = v;
        }
        __syncthreads();
        #pragma unroll
        for (int ky = 0; ky < 4; ky++) {
            #pragma unroll
            for (int kx = 0; kx < 4; kx++) {
                const ulonglong2* w4 = (const ulonglong2*)&ws[(ic * 16 + ky * 4 + kx) * COUT];
                ull w2[COUT / 2];
                #pragma unroll
                for (int jj = 0; jj < COUT / 4; jj++) {
                    ulonglong2 ww = w4[jj];
                    w2[2 * jj] = ww.x; w2[2 * jj + 1] = ww.y;
                }
                #pragma unroll
                for (int dy = 0; dy < PY; dy++) {
                    #pragma unroll
                    for (int dx = 0; dx < PX; dx++) {
                        float v = tile[(2 * (OYl + dy) + ky) * TCS + 2 * (OXl + dx) + kx];
                        ull v2 = pk2(v, v);
                        int pi = dy * PX + dx;
                        #pragma unroll
                        for (int j = 0; j < COUT / 2; j++)
                            acc2[pi][j] = fma2(v2, w2[j], acc2[pi][j]);
                    }
                }
            }
        }
    }

    float acc[NPIX][COUT];
    #pragma unroll
    for (int p = 0; p < NPIX; p++)
        #pragma unroll
        for (int j = 0; j < COUT / 2; j++) upk2(acc2[p][j], acc[p][2*j], acc[p][2*j+1]);

    float* ob = out + ((size_t)b * COUT) * HO * WO;
    #pragma unroll
    for (int oc = 0; oc < COUT; oc++) {
        float bz = bias[oc];
        #pragma unroll
        for (int dy = 0; dy < PY; dy++) {
            #pragma unroll
            for (int dx = 0; dx < PX; dx++) {
                int pi = dy * PX + dx;
                float v = acc[pi][oc] + bz;
                acc[pi][oc] = v;
                ob[(size_t)oc * HO * WO + (size_t)(OY + dy) * WO + OX + dx] = v;
            }
        }
    }

    int lane = tid & 31;
    #pragma unroll
    for (int oc = 0; oc < COUT; oc++) {
        float s = 0.f, qs = 0.f;
        #pragma unroll
        for (int p = 0; p < NPIX; p++) { float v = acc[p][oc]; s += v; qs = fmaf(v, v, qs); }
        s = warp_red(s); qs = warp_red(qs);
        if (lane == 0) { atomicAdd(&ssum[oc], s); atomicAdd(&ssq[oc], qs); }
    }
    __syncthreads();
    if (tid < COUT) { atomicAdd(&gsum[tid], ssum[tid]); atomicAdd(&gsq[tid], ssq[tid]); }
}

// ---------------- transposed conv via parity decomposition ----------------
// Output parity class (cy,cx) = blockIdx.z; each class is a stride-1 conv with
// a fixed 2x2 subset of the 4x4 kernel. Thread computes PP x PP same-parity outputs.
template<int CIN, int COUT, int HO, int WO, int PP, bool PRE>
__global__ void convT_k(const float* __restrict__ in, const float* __restrict__ w,
                        const float* __restrict__ bias,
                        const float* __restrict__ gsum_in, const float* __restrict__ gsq_in,
                        const float* __restrict__ gam, const float* __restrict__ bet, float cnt,
                        float* __restrict__ out,
                        float* __restrict__ gsum, float* __restrict__ gsq) {
    constexpr int HI = HO / 2, WI = WO / 2;
    constexpr int HH = HO / 2, WW = WO / 2;       // parity-index space
    constexpr int TBX = 16, TBY = 8;
    constexpr int CX = WW / (TBX * PP), CY = HH / (TBY * PP);
    constexpr int NPIX = PP * PP;
    constexpr int PS = PP + 1;
    __shared__ float ws[CIN * 16 * COUT];   // [ic][ky*4+kx][oc]
    __shared__ float ssum[COUT], ssq[COUT];
    __shared__ float ssc[(PRE ? CIN : 1)], ssh[(PRE ? CIN : 1)];
    int tid = threadIdx.x;
    for (int i = tid; i < CIN * 16 * COUT; i += 128) {
        int oc = i % COUT; int r = i / COUT; int k = r & 15; int ic = r >> 4;
        ws[i] = w[(ic * COUT + oc) * 16 + k];   // torch layout [in][out][kh][kw]
    }
    if (tid < COUT) { ssum[tid] = 0.f; ssq[tid] = 0.f; }
    if constexpr (PRE) bn_block<CIN>(gsum_in, gsq_in, gam, bet, cnt, ssc, ssh, tid);
    __syncthreads();

    int b = blockIdx.y;
    int cz = blockIdx.z; int cy = cz >> 1, cx = cz & 1;
    int chX = blockIdx.x % CX, chY = blockIdx.x / CX;
    int tx = tid % TBX, ty = tid / TBX;
    int Y0 = (chY * TBY + ty) * PP, X0 = (chX * TBX + tx) * PP;

    float accS[NPIX][(COUT % 4 == 0) ? 1 : COUT];
    ull acc2[NPIX][(COUT % 4 == 0) ? COUT / 2 : 1];
    if constexpr (COUT % 4 == 0) {
        #pragma unroll
        for (int p = 0; p < NPIX; p++)
            #pragma unroll
            for (int j = 0; j < COUT / 2; j++) acc2[p][j] = 0ull;
    } else {
        #pragma unroll
        for (int p = 0; p < NPIX; p++)
            #pragma unroll
            for (int oc = 0; oc < COUT; oc++) accS[p][oc] = 0.f;
    }

    const float* inb = in + (size_t)b * CIN * HI * WI;
    #pragma unroll 1
    for (int ic = 0; ic < CIN; ic++) {
        const float* ip = inb + (size_t)ic * HI * WI;
        float sc = 1.f, sh = 0.f;
        if constexpr (PRE) { sc = ssc[ic]; sh = ssh[ic]; }
        float p[PS][PS];
        #pragma unroll
        for (int r = 0; r < PS; r++) {
            int gy = Y0 + cy - 1 + r;
            bool yok = (unsigned)gy < (unsigned)HI;
            const float* rp = ip + (size_t)gy * WI;
            #pragma unroll
            for (int c = 0; c < PS; c++) {
                int gx = X0 + cx - 1 + c;
                float v = 0.f;
                if (yok && (unsigned)gx < (unsigned)WI) {
                    v = rp[gx];
                    if constexpr (PRE) v = fmaxf(fmaf(v, sc, sh), 0.f);
                }
                p[r][c] = v;
            }
        }
        #pragma unroll
        for (int t = 0; t < 2; t++) {
            #pragma unroll
            for (int s = 0; s < 2; s++) {
                int ky = (1 - cy) + 2 * t, kx = (1 - cx) + 2 * s;
                const float* wr = &ws[(ic * 16 + ky * 4 + kx) * COUT];
                if constexpr (COUT % 4 == 0) {
                    const ulonglong2* w4 = (const ulonglong2*)wr;
                    ull w2[COUT / 2];
                    #pragma unroll
                    for (int jj = 0; jj < COUT / 4; jj++) {
                        ulonglong2 ww = w4[jj];
                        w2[2 * jj] = ww.x; w2[2 * jj + 1] = ww.y;
                    }
                    #pragma unroll
                    for (int dy = 0; dy < PP; dy++) {
                        #pragma unroll
                        for (int dx = 0; dx < PP; dx++) {
                            float v = p[dy + 1 - t][dx + 1 - s];
                            ull v2 = pk2(v, v);
                            int pi = dy * PP + dx;
                            #pragma unroll
                            for (int j = 0; j < COUT / 2; j++)
                                acc2[pi][j] = fma2(v2, w2[j], acc2[pi][j]);
                        }
                    }
                } else {
                    float wv = wr[0];
                    #pragma unroll
                    for (int dy = 0; dy < PP; dy++)
                        #pragma unroll
                        for (int dx = 0; dx < PP; dx++)
                            accS[dy * PP + dx][0] = fmaf(p[dy + 1 - t][dx + 1 - s], wv,
                                                         accS[dy * PP + dx][0]);
                }
            }
        }
    }

    float acc[NPIX][COUT];
    if constexpr (COUT % 4 == 0) {
        #pragma unroll
        for (int p = 0; p < NPIX; p++)
            #pragma unroll
            for (int j = 0; j < COUT / 2; j++) upk2(acc2[p][j], acc[p][2*j], acc[p][2*j+1]);
    } else {
        #pragma unroll
        for (int p = 0; p < NPIX; p++)
            #pragma unroll
            for (int oc = 0; oc < COUT; oc++) acc[p][oc] = accS[p][oc];
    }

    float* ob = out + ((size_t)b * COUT) * HO * WO;
    #pragma unroll
    for (int oc = 0; oc < COUT; oc++) {
        float bz = bias[oc];
        #pragma unroll
        for (int dy = 0; dy < PP; dy++) {
            #pragma unroll
            for (int dx = 0; dx < PP; dx++) {
                int pi = dy * PP + dx;
                float v = acc[pi][oc] + bz;
                acc[pi][oc] = v;
                int oy = 2 * (Y0 + dy) + cy, ox = 2 * (X0 + dx) + cx;
                ob[(size_t)oc * HO * WO + (size_t)oy * WO + ox] = v;
            }
        }
    }

    int lane = tid & 31;
    #pragma unroll
    for (int oc = 0; oc < COUT; oc++) {
        float s = 0.f, qs = 0.f;
        #pragma unroll
        for (int p = 0; p < NPIX; p++) { float v = acc[p][oc]; s += v; qs = fmaf(v, v, qs); }
        s = warp_red(s); qs = warp_red(qs);
        if (lane == 0) { atomicAdd(&ssum[oc], s); atomicAdd(&ssq[oc], qs); }
    }
    __syncthreads();
    if (tid < COUT) { atomicAdd(&gsum[tid], ssum[tid]); atomicAdd(&gsq[tid], ssq[tid]); }
}

// ---------------- quantizer: 1 thread per vector, codebook tiled through shared ----------------
__global__ void quant_k(const float* __restrict__ q_raw, const float* __restrict__ cb,
                        float* __restrict__ qout, float* __restrict__ idx_out,
                        const float* __restrict__ gsum_in, const float* __restrict__ gsq_in,
                        const float* __restrict__ gam, const float* __restrict__ bet) {
    __shared__ float cbs[128 * 32];
    __shared__ float cns[128];
    __shared__ float ssc[32], ssh[32];
    int tid = threadIdx.x;
    bn_block<32>(gsum_in, gsq_in, gam, bet, 65536.f, ssc, ssh, tid);
    __syncthreads();

    int vec = blockIdx.x * 256 + tid;
    int b = vec >> 10, hw = vec & 1023;

    const float* base = q_raw + ((size_t)b * 32) * 1024 + hw;
    ull z2[16];
    #pragma unroll
    for (int j = 0; j < 16; j++) {
        float v0 = base[(size_t)(2*j)   * 1024];
        float v1 = base[(size_t)(2*j+1) * 1024];
        v0 = fmaxf(fmaf(v0, ssc[2*j],   ssh[2*j]),   0.f);
        v1 = fmaxf(fmaf(v1, ssc[2*j+1], ssh[2*j+1]), 0.f);
        z2[j] = pk2(v0, v1);
    }

    float best = 3.4e38f; int bi = 0;
    #pragma unroll 1
    for (int t = 0; t < 4; t++) {
        __syncthreads();
        const float4* src = (const float4*)(cb + (size_t)t * 128 * 32);
        float4* dst = (float4*)cbs;
        #pragma unroll
        for (int j = 0; j < 4; j++) dst[tid + 256 * j] = src[tid + 256 * j];
        if (tid < 128) cns[tid] = g_cnorm[t * 128 + tid];
        __syncthreads();
        #pragma unroll 1
        for (int k = 0; k < 128; k += 2) {
            const ulonglong2* cp0 = (const ulonglong2*)(cbs + k * 32);
            const ulonglong2* cp1 = (const ulonglong2*)(cbs + (k + 1) * 32);
            ull a0 = 0ull, a1 = 0ull, b0 = 0ull, b1 = 0ull;
            #pragma unroll
            for (int i = 0; i < 8; i++) {
                ulonglong2 c0 = cp0[i];
                ulonglong2 c1 = cp1[i];
                a0 = fma2(z2[2*i],   c0.x, a0);
                a1 = fma2(z2[2*i+1], c0.y, a1);
                b0 = fma2(z2[2*i],   c1.x, b0);
                b1 = fma2(z2[2*i+1], c1.y, b1);
            }
            float x0, x1, x2, x3, y0, y1, y2, y3;
            upk2(a0, x0, x1); upk2(a1, x2, x3);
            upk2(b0, y0, y1); upk2(b1, y2, y3);
            float dot0 = (x0 + x1) + (x2 + x3);
            float dot1 = (y0 + y1) + (y2 + y3);
            float s0 = cns[k]     - 2.f * dot0;
            float s1 = cns[k + 1] - 2.f * dot1;
            if (s0 < best) { best = s0; bi = t * 128 + k; }
            if (s1 < best) { best = s1; bi = t * 128 + k + 1; }
        }
    }

    idx_out[vec] = (float)bi;
    float* qb = qout + ((size_t)b * 32) * 1024 + hw;
    const float4* cbest = (const float4*)(cb + (size_t)bi * 32);
    float sse = 0.f;
    #pragma unroll
    for (int j = 0; j < 8; j++) {
        float4 c4 = __ldg(&cbest[j]);
        float z0, z1, z2f, z3;
        upk2(z2[2*j], z0, z1); upk2(z2[2*j+1], z2f, z3);
        qb[(size_t)(4*j+0) * 1024] = c4.x;
        qb[(size_t)(4*j+1) * 1024] = c4.y;
        qb[(size_t)(4*j+2) * 1024] = c4.z;
        qb[(size_t)(4*j+3) * 1024] = c4.w;
        float e0 = c4.x - z0, e1 = c4.y - z1;
        float e2 = c4.z - z2f, e3 = c4.w - z3;
        sse = fmaf(e0, e0, fmaf(e1, e1, fmaf(e2, e2, fmaf(e3, e3, sse))));
    }
    sse = warp_red(sse);
    if ((tid & 31) == 0) atomicAdd(&g_loss[0], sse);
}

// ---------------- final: BN6-apply (computed in-block), write output, recon SSE ----------------
__global__ void final_k(const float* __restrict__ x, float* __restrict__ dout,
                        const float* __restrict__ gsum_in, const float* __restrict__ gsq_in,
                        const float* __restrict__ gam, const float* __restrict__ bet) {
    __shared__ float wsum[8];
    __shared__ float sbn[2];
    if (threadIdx.x == 0) {
        float m = gsum_in[0] * (1.f / 4194304.f);
        float var = gsq_in[0] * (1.f / 4194304.f) - m * m;
        float s = gam[0] * rsqrtf(var + 1e-5f);
        sbn[0] = s; sbn[1] = bet[0] - m * s;
    }
    __syncthreads();
    int i = blockIdx.x * blockDim.x + threadIdx.x;
    float y = fmaf(g_buf7[i], sbn[0], sbn[1]);
    dout[i] = y;
    float d = x[i] - y;
    float s = d * d;
    s = warp_red(s);
    if ((threadIdx.x & 31) == 0) wsum[threadIdx.x >> 5] = s;
    __syncthreads();
    if (threadIdx.x == 0) {
        float t = 0.f;
        #pragma unroll
        for (int j = 0; j < 8; j++) t += wsum[j];
        atomicAdd(&g_loss[1], t);
    }
}

__global__ void loss_k(float* __restrict__ dloss) {
    dloss[0] = 1.2f * g_loss[0] * (1.f / 2097152.f) + g_loss[1] * (1.f / 4194304.f);
}

// ---------------- launcher ----------------
extern "C" void kernel_launch(void* const* d_in, const int* in_sizes, int n_in,
                              void* d_out, int out_size) {
    const float* x      = (const float*)d_in[0];
    const float* enc_w1 = (const float*)d_in[1];
    const float* enc_b1 = (const float*)d_in[2];
    const float* enc_w2 = (const float*)d_in[3];
    const float* enc_b2 = (const float*)d_in[4];
    const float* enc_w3 = (const float*)d_in[5];
    const float* enc_b3 = (const float*)d_in[6];
    const float* enc_g1 = (const float*)d_in[7];
    const float* enc_be1= (const float*)d_in[8];
    const float* enc_g2 = (const float*)d_in[9];
    const float* enc_be2= (const float*)d_in[10];
    const float* enc_g3 = (const float*)d_in[11];
    const float* enc_be3= (const float*)d_in[12];
    const float* cb     = (const float*)d_in[13];
    const float* dec_w1 = (const float*)d_in[14];
    const float* dec_b1 = (const float*)d_in[15];
    const float* dec_w2 = (const float*)d_in[16];
    const float* dec_b2 = (const float*)d_in[17];
    const float* dec_w3 = (const float*)d_in[18];
    const float* dec_b3 = (const float*)d_in[19];
    const float* dec_g1 = (const float*)d_in[20];
    const float* dec_be1= (const float*)d_in[21];
    const float* dec_g2 = (const float*)d_in[22];
    const float* dec_be2= (const float*)d_in[23];
    const float* dec_g3 = (const float*)d_in[24];
    const float* dec_be3= (const float*)d_in[25];

    float* o = (float*)d_out;
    float* o_loss = o + 4194304;
    float* o_idx  = o + 4194305;

    static float *buf1,*buf2,*buf3,*buf4,*buf5,*buf6,*buf7,*sum,*sq;
    static bool init = false;
    if (!init) {
        cudaGetSymbolAddress((void**)&buf1, g_buf1);
        cudaGetSymbolAddress((void**)&buf2, g_buf2);
        cudaGetSymbolAddress((void**)&buf3, g_buf3);
        cudaGetSymbolAddress((void**)&buf4, g_buf4);
        cudaGetSymbolAddress((void**)&buf5, g_buf5);
        cudaGetSymbolAddress((void**)&buf6, g_buf6);
        cudaGetSymbolAddress((void**)&buf7, g_buf7);
        cudaGetSymbolAddress((void**)&sum,  g_sum);
        cudaGetSymbolAddress((void**)&sq,   g_sq);
        init = true;
    }

    zero_k<<<1, 256>>>();                                         // launch 1
    cnorm_k<<<2, 256>>>(cb);                                      // launch 2

    // encoder: tiles 32x16 out per block (16x8 threads, 2x2 px); conv3 is 32x8 (1x2 px)
    conv_s2_k<1,16,128,128,2,2,false><<<dim3(4*8, NB), 128>>>(         // launch 3
        x, enc_w1, enc_b1, nullptr, nullptr, nullptr, nullptr, 0.f,
        buf1, sum + 0, sq + 0);
    conv_s2_k<16,16,64,64,2,2,true><<<dim3(2*4, NB), 128>>>(           // launch 4
        buf1, enc_w2, enc_b2, sum + 0, sq + 0, enc_g1, enc_be1, 1048576.f,
        buf2, sum + 32, sq + 32);
    conv_s2_k<16,32,32,32,1,2,true><<<dim3(1*4, NB), 128>>>(           // launch 5
        buf2, enc_w3, enc_b3, sum + 32, sq + 32, enc_g2, enc_be2, 262144.f,
        buf3, sum + 64, sq + 64);

    // quantizer — launch 6 (the one ncu -s 5 -c 1 captures)
    quant_k<<<256, 256>>>(buf3, cb, buf4, o_idx, sum + 64, sq + 64, enc_g3, enc_be3);

    // decoder (parity-decomposed convT; blockIdx.z = parity class)
    convT_k<32,16,64,64,2,false><<<dim3(1*2, NB, 4), 128>>>(           // launch 7
        buf4, dec_w1, dec_b1, nullptr, nullptr, nullptr, nullptr, 0.f,
        buf5, sum + 96, sq + 96);
    convT_k<16,16,128,128,2,true><<<dim3(2*4, NB, 4), 128>>>(          // launch 8
        buf5, dec_w2, dec_b2, sum + 96, sq + 96, dec_g1, dec_be1, 262144.f,
        buf6, sum + 128, sq + 128);
    convT_k<16,1,256,256,4,true><<<dim3(2*4, NB, 4), 128>>>(           // launch 9
        buf6, dec_w3, dec_b3, sum + 128, sq + 128, dec_g2, dec_be2, 1048576.f,
        buf7, sum + 160, sq + 160);

    // output + losses
    final_k<<<16384, 256>>>(x, o, sum + 160, sq + 160, dec_g3, dec_be3);  // launch 10
    loss_k<<<1, 1>>>(o_loss);                                              // launch 11
}